// round 4
// baseline (speedup 1.0000x reference)
#include <cuda_runtime.h>
#include <cstdint>

#define BATCH 16384
#define H 256
#define OUTD 10
#define IND 784
#define TSTEPS 50

typedef unsigned long long ull;

// -------- device scratch (static allocation per harness rules) --------
__device__ float g_X[BATCH * H];            // rho(data) @ W4.T + b4  (time-invariant)
__device__ float g_W2T[H * H];              // W2 transposed once
__device__ float g_s0[2][BATCH * OUTD];     // ping-pong state
__device__ float g_s1[2][BATCH * H];
__device__ float g_s2[2][BATCH * H];

__device__ __forceinline__ float rho_f(float x) { return fminf(fmaxf(x, 0.0f), 1.0f); }

__device__ __forceinline__ ull pack2(float a, float b) {
    ull r; asm("mov.b64 %0, {%1, %2};" : "=l"(r) : "f"(a), "f"(b)); return r;
}
__device__ __forceinline__ void fma2(ull &d, ull a, ull b) {
    asm("fma.rn.f32x2 %0, %1, %2, %0;" : "+l"(d) : "l"(a), "l"(b));
}
__device__ __forceinline__ float2 unpack2(ull v) {
    float2 f; asm("mov.b64 {%0, %1}, %2;" : "=f"(f.x), "=f"(f.y) : "l"(v)); return f;
}
__device__ __forceinline__ void cpasync16(float* dst, const float* src) {
    unsigned d = (unsigned)__cvta_generic_to_shared(dst);
    asm volatile("cp.async.cg.shared.global [%0], [%1], 16;" :: "r"(d), "l"(src));
}
__device__ __forceinline__ void cpasync_commit() {
    asm volatile("cp.async.commit_group;");
}
__device__ __forceinline__ void cpasync_wait0() {
    asm volatile("cp.async.wait_group 0;");
}

// ---------------- init: copy state in, transpose W2 ----------------
__global__ void __launch_bounds__(256) init_kernel(
    const float* __restrict__ s0, const float* __restrict__ s1,
    const float* __restrict__ s2, const float* __restrict__ W2)
{
    int idx = blockIdx.x * 256 + threadIdx.x;          // 0 .. BATCH*H/4-1
    ((float4*)g_s1[0])[idx] = ((const float4*)s1)[idx];
    ((float4*)g_s2[0])[idx] = ((const float4*)s2)[idx];
    if (idx < BATCH * OUTD / 4)
        ((float4*)g_s0[0])[idx] = ((const float4*)s0)[idx];
    if (idx < H * H) {
        int k = idx >> 8, j = idx & 255;
        g_W2T[idx] = W2[j * H + k];                    // W2T[k][j] = W2[j][k]
    }
}

// ---------------- prefix: X = rho(data) @ W4.T + b4 ----------------
__global__ void __launch_bounds__(256) x_kernel(
    const float* __restrict__ data, const float* __restrict__ W4,
    const float* __restrict__ b4)
{
    __shared__ float As[16 * 66];
    __shared__ float Bs[16 * 66];
    const int tid = threadIdx.x;
    const int i0 = blockIdx.x * 64, j0 = blockIdx.y * 64;
    const int tx = tid & 15, ty = tid >> 4;
    const int kk = tid & 15, rr = tid >> 4;

    ull acc[4][2] = {};
    for (int k0 = 0; k0 < IND; k0 += 16) {
#pragma unroll
        for (int q = 0; q < 4; q++) {
            int r = rr + q * 16;
            As[kk * 66 + r] = rho_f(data[(size_t)(i0 + r) * IND + k0 + kk]);
            Bs[kk * 66 + r] = W4[(size_t)(j0 + r) * IND + k0 + kk];
        }
        __syncthreads();
#pragma unroll
        for (int k = 0; k < 16; k++) {
            ull a[4];
#pragma unroll
            for (int i = 0; i < 4; i++) {
                float av = As[k * 66 + ty * 4 + i];
                a[i] = pack2(av, av);
            }
            const ull* wp0 = (const ull*)(Bs + k * 66 + tx * 2);
            const ull* wp1 = (const ull*)(Bs + k * 66 + 32 + tx * 2);
            ull w0 = *wp0, w1 = *wp1;
#pragma unroll
            for (int i = 0; i < 4; i++) { fma2(acc[i][0], a[i], w0); fma2(acc[i][1], a[i], w1); }
        }
        __syncthreads();
    }
#pragma unroll
    for (int i = 0; i < 4; i++) {
        size_t row = (size_t)i0 + ty * 4 + i;
        float2 p0 = unpack2(acc[i][0]), p1 = unpack2(acc[i][1]);
        int j0a = j0 + tx * 2, j0b = j0 + 32 + tx * 2;
        *(float2*)(g_X + row * H + j0a) = make_float2(p0.x + b4[j0a], p0.y + b4[j0a + 1]);
        *(float2*)(g_X + row * H + j0b) = make_float2(p1.x + b4[j0b], p1.y + b4[j0b + 1]);
    }
}

// ---------------- fused step kernel ----------------
#define ROWS 64
#define LD   260          // smem row pitch (floats): float4-aligned, bank-spread
#define BK   32
#define NTHR 512
#define STEP_SMEM_FLOATS (2 * ROWS * LD + 2 * BK * H + OUTD * H + ROWS * OUTD)
#define STEP_SMEM_BYTES  (STEP_SMEM_FLOATS * 4)

// Thread (tx, ry): rows {2*ry, 2*ry+1}, col quads {4*tx + 64*p : p=0..3}.
// acc[i][2p], acc[i][2p+1] hold cols 4tx+64p .. +3 for row 2ry+i.
// Weight LDS.128: 16 tx lanes -> 16 consecutive 16B chunks (conflict-free),
// ry halves broadcast-merge. W chunks double-buffered via cp.async.
// NOTE column stride: ulonglong2 = 4 floats, so +64 floats = wr[p * 16].
__device__ __forceinline__ void mm_accum(
    ull (&acc)[2][8], const float* __restrict__ RS,
    const float* __restrict__ Wglob, float* Wc,
    int tid, int rbase, int cb)
{
    const int e = tid * 4;  // this thread's 16B slot within a 32x256 chunk (4 slots)
    // prefetch chunk 0 into buffer 0
#pragma unroll
    for (int q = 0; q < 4; q++)
        cpasync16(Wc + q * 2048 + e, Wglob + q * 2048 + e);
    cpasync_commit();

#pragma unroll 1
    for (int k0 = 0; k0 < H; k0 += BK) {
        float* cur = Wc + ((k0 >> 5) & 1) * (BK * H);
        float* nxt = Wc + (((k0 >> 5) & 1) ^ 1) * (BK * H);
        cpasync_wait0();
        __syncthreads();
        if (k0 + BK < H) {
#pragma unroll
            for (int q = 0; q < 4; q++)
                cpasync16(nxt + q * 2048 + e, Wglob + (size_t)(k0 + BK) * H + q * 2048 + e);
            cpasync_commit();
        }
#pragma unroll 8
        for (int kk = 0; kk < BK; kk++) {
            float a0 = RS[(rbase + 0) * LD + k0 + kk];
            float a1 = RS[(rbase + 1) * LD + k0 + kk];
            ull A0 = pack2(a0, a0), A1 = pack2(a1, a1);
            const ulonglong2* wr = (const ulonglong2*)(cur + kk * H + cb);
#pragma unroll
            for (int p = 0; p < 4; p++) {
                ulonglong2 w = wr[p * 16];       // +64 floats per p (16 x 16B)
                fma2(acc[0][2 * p], A0, w.x); fma2(acc[0][2 * p + 1], A0, w.y);
                fma2(acc[1][2 * p], A1, w.x); fma2(acc[1][2 * p + 1], A1, w.y);
            }
        }
    }
    __syncthreads();
}

__global__ void __launch_bounds__(NTHR, 1) step_kernel(
    int inbuf, int last, float* __restrict__ dout,
    const float* __restrict__ W2, const float* __restrict__ W0,
    const float* __restrict__ b0, const float* __restrict__ b2)
{
    extern __shared__ float sm[];
    float* RS1 = sm;                       // [ROWS][LD]  rho(s1_old)
    float* RS2 = RS1 + ROWS * LD;          // [ROWS][LD]  rho(s2_old)
    float* Wc  = RS2 + ROWS * LD;          // [2][BK][H]  weight chunks (double buf)
    float* W0s = Wc + 2 * BK * H;          // [OUTD][H]
    float* RS0 = W0s + OUTD * H;           // [ROWS][OUTD] rho(s0_old)

    const int tid = threadIdx.x;
    const size_t row0 = (size_t)blockIdx.x * ROWS;

    const float* __restrict__ s0in = g_s0[inbuf];
    const float* __restrict__ s1in = g_s1[inbuf];
    const float* __restrict__ s2in = g_s2[inbuf];
    float* s0out = last ? dout : g_s0[inbuf ^ 1];
    float* s1out = last ? (dout + BATCH * OUTD) : g_s1[inbuf ^ 1];
    float* s2out = last ? (dout + BATCH * OUTD + (size_t)BATCH * H) : g_s2[inbuf ^ 1];

    // ---- stage rho(state) tiles ----
#pragma unroll
    for (int q = 0; q < 8; q++) {
        int e = (q * NTHR + tid) * 4;
        int r = e >> 8, c = e & 255;
        float4 v = *(const float4*)(s1in + row0 * H + e);
        v.x = rho_f(v.x); v.y = rho_f(v.y); v.z = rho_f(v.z); v.w = rho_f(v.w);
        *(float4*)(RS1 + r * LD + c) = v;
        float4 u = *(const float4*)(s2in + row0 * H + e);
        u.x = rho_f(u.x); u.y = rho_f(u.y); u.z = rho_f(u.z); u.w = rho_f(u.w);
        *(float4*)(RS2 + r * LD + c) = u;
    }
    for (int i = tid; i < ROWS * OUTD; i += NTHR)
        RS0[i] = rho_f(s0in[row0 * OUTD + i]);
    for (int i = tid; i < OUTD * H; i += NTHR)
        W0s[i] = W0[i];
    __syncthreads();

    const int tx = tid & 15, ry = tid >> 4;   // ry 0..31
    const int rbase = ry * 2;                 // 2 rows per thread
    const int cb = tx * 4;                    // quads at cb + 64*p

    ull acc[2][8];

    // ================= stage A: s2 update =================
    // n2pre = X + rho(s1) @ W2        (W2[k][j], row-major chunks)
#pragma unroll
    for (int i = 0; i < 2; i++)
#pragma unroll
        for (int p = 0; p < 8; p++) acc[i][p] = 0ULL;
    mm_accum(acc, RS1, W2, Wc, tid, rbase, cb);

#pragma unroll
    for (int i = 0; i < 2; i++) {
        size_t r = row0 + rbase + i;
#pragma unroll
        for (int p = 0; p < 4; p++) {
            int c = cb + 64 * p;
            float4 xo = *(const float4*)(g_X + r * H + c);
            float4 so = *(const float4*)(s2in + r * H + c);
            float2 q0 = unpack2(acc[i][2 * p]), q1 = unpack2(acc[i][2 * p + 1]);
            float4 ov;
            ov.x = rho_f(0.5f * (so.x + ((so.x >= 0.f && so.x <= 1.f) ? (xo.x + q0.x) : 0.f)));
            ov.y = rho_f(0.5f * (so.y + ((so.y >= 0.f && so.y <= 1.f) ? (xo.y + q0.y) : 0.f)));
            ov.z = rho_f(0.5f * (so.z + ((so.z >= 0.f && so.z <= 1.f) ? (xo.z + q1.x) : 0.f)));
            ov.w = rho_f(0.5f * (so.w + ((so.w >= 0.f && so.w <= 1.f) ? (xo.w + q1.y) : 0.f)));
            *(float4*)(s2out + r * H + c) = ov;
        }
    }

    // ================= stage B: s1 update =================
    // n1pre = b2 + rho(s2) @ W2.T + rho(s0) @ W0   (W2.T via g_W2T)
#pragma unroll
    for (int p = 0; p < 4; p++) {
        float4 bv = *(const float4*)(b2 + cb + 64 * p);
        ull b01 = pack2(bv.x, bv.y), b23 = pack2(bv.z, bv.w);
        acc[0][2 * p] = b01; acc[0][2 * p + 1] = b23;
        acc[1][2 * p] = b01; acc[1][2 * p + 1] = b23;
    }
    mm_accum(acc, RS2, g_W2T, Wc, tid, rbase, cb);

#pragma unroll
    for (int o = 0; o < OUTD; o++) {
        float a0 = RS0[(rbase + 0) * OUTD + o];
        float a1 = RS0[(rbase + 1) * OUTD + o];
        ull A0 = pack2(a0, a0), A1 = pack2(a1, a1);
        const ulonglong2* wr = (const ulonglong2*)(W0s + o * H + cb);
#pragma unroll
        for (int p = 0; p < 4; p++) {
            ulonglong2 w = wr[p * 16];           // +64 floats per p
            fma2(acc[0][2 * p], A0, w.x); fma2(acc[0][2 * p + 1], A0, w.y);
            fma2(acc[1][2 * p], A1, w.x); fma2(acc[1][2 * p + 1], A1, w.y);
        }
    }

#pragma unroll
    for (int i = 0; i < 2; i++) {
        size_t r = row0 + rbase + i;
#pragma unroll
        for (int p = 0; p < 4; p++) {
            int c = cb + 64 * p;
            float4 so = *(const float4*)(s1in + r * H + c);
            float2 q0 = unpack2(acc[i][2 * p]), q1 = unpack2(acc[i][2 * p + 1]);
            float4 ov;
            ov.x = rho_f(0.5f * (so.x + ((so.x >= 0.f && so.x <= 1.f) ? q0.x : 0.f)));
            ov.y = rho_f(0.5f * (so.y + ((so.y >= 0.f && so.y <= 1.f) ? q0.y : 0.f)));
            ov.z = rho_f(0.5f * (so.z + ((so.z >= 0.f && so.z <= 1.f) ? q1.x : 0.f)));
            ov.w = rho_f(0.5f * (so.w + ((so.w >= 0.f && so.w <= 1.f) ? q1.y : 0.f)));
            *(float4*)(s1out + r * H + c) = ov;
        }
    }

    // ================= s0 update =================
    // n0 = b0 + rho(s1) @ W0.T ; s0' = clip(0.5*(s0 + n0))   (no rhop gate)
    for (int idx = tid; idx < ROWS * OUTD; idx += NTHR) {
        int o = idx >> 6;          // warp shares o -> W0s reads broadcast
        int r = idx & 63;
        float av = 0.f;
#pragma unroll 8
        for (int k = 0; k < H; k += 4) {
            float4 a = *(const float4*)(RS1 + r * LD + k);
            float4 w = *(const float4*)(W0s + o * H + k);
            av = fmaf(a.x, w.x, fmaf(a.y, w.y, fmaf(a.z, w.z, fmaf(a.w, w.w, av))));
        }
        av += b0[o];
        float s = s0in[(row0 + r) * OUTD + o];
        s0out[(row0 + r) * OUTD + o] = rho_f(0.5f * (s + av));
    }
}

// ---------------- launch ----------------
extern "C" void kernel_launch(void* const* d_in, const int* in_sizes, int n_in,
                              void* d_out, int out_size)
{
    (void)in_sizes; (void)n_in; (void)out_size;
    const float* data = (const float*)d_in[0];
    const float* s0   = (const float*)d_in[1];
    const float* s1   = (const float*)d_in[2];
    const float* s2   = (const float*)d_in[3];
    const float* W0   = (const float*)d_in[4];
    const float* b0   = (const float*)d_in[5];
    const float* W2   = (const float*)d_in[6];
    const float* b2   = (const float*)d_in[7];
    const float* W4   = (const float*)d_in[8];
    const float* b4   = (const float*)d_in[9];
    float* out = (float*)d_out;

    cudaFuncSetAttribute(step_kernel, cudaFuncAttributeMaxDynamicSharedMemorySize,
                         STEP_SMEM_BYTES);

    init_kernel<<<(BATCH * H / 4) / 256, 256>>>(s0, s1, s2, W2);
    x_kernel<<<dim3(BATCH / 64, H / 64), 256>>>(data, W4, b4);
    for (int t = 0; t < TSTEPS; t++) {
        step_kernel<<<BATCH / ROWS, NTHR, STEP_SMEM_BYTES>>>(
            t & 1, t == TSTEPS - 1, out, W2, W0, b0, b2);
    }
}

// round 5
// speedup vs baseline: 1.0058x; 1.0058x over previous
#include <cuda_runtime.h>
#include <cstdint>

#define BATCH 16384
#define H 256
#define OUTD 10
#define IND 784
#define TSTEPS 50

typedef unsigned long long ull;

// -------- device scratch (static allocation per harness rules) --------
__device__ float g_X[BATCH * H];            // rho(data) @ W4.T + b4  (time-invariant)
__device__ float g_W2T[H * H];              // W2 transposed once
__device__ float g_s0[2][BATCH * OUTD];     // ping-pong state
__device__ float g_s1[2][BATCH * H];
__device__ float g_s2[2][BATCH * H];

__device__ __forceinline__ float rho_f(float x) { return fminf(fmaxf(x, 0.0f), 1.0f); }

__device__ __forceinline__ ull pack2(float a, float b) {
    ull r; asm("mov.b64 %0, {%1, %2};" : "=l"(r) : "f"(a), "f"(b)); return r;
}
__device__ __forceinline__ void fma2(ull &d, ull a, ull b) {
    asm("fma.rn.f32x2 %0, %1, %2, %0;" : "+l"(d) : "l"(a), "l"(b));
}
__device__ __forceinline__ float2 unpack2(ull v) {
    float2 f; asm("mov.b64 {%0, %1}, %2;" : "=f"(f.x), "=f"(f.y) : "l"(v)); return f;
}
__device__ __forceinline__ void cpasync16(float* dst, const float* src) {
    unsigned d = (unsigned)__cvta_generic_to_shared(dst);
    asm volatile("cp.async.cg.shared.global [%0], [%1], 16;" :: "r"(d), "l"(src));
}
__device__ __forceinline__ void cpasync_commit() {
    asm volatile("cp.async.commit_group;");
}
__device__ __forceinline__ void cpasync_wait0() {
    asm volatile("cp.async.wait_group 0;");
}

// ---------------- init: copy state in, transpose W2 ----------------
__global__ void __launch_bounds__(256) init_kernel(
    const float* __restrict__ s0, const float* __restrict__ s1,
    const float* __restrict__ s2, const float* __restrict__ W2)
{
    int idx = blockIdx.x * 256 + threadIdx.x;          // 0 .. BATCH*H/4-1
    ((float4*)g_s1[0])[idx] = ((const float4*)s1)[idx];
    ((float4*)g_s2[0])[idx] = ((const float4*)s2)[idx];
    if (idx < BATCH * OUTD / 4)
        ((float4*)g_s0[0])[idx] = ((const float4*)s0)[idx];
    if (idx < H * H) {
        int k = idx >> 8, j = idx & 255;
        g_W2T[idx] = W2[j * H + k];                    // W2T[k][j] = W2[j][k]
    }
}

// ---------------- prefix: X = rho(data) @ W4.T + b4 ----------------
__global__ void __launch_bounds__(256) x_kernel(
    const float* __restrict__ data, const float* __restrict__ W4,
    const float* __restrict__ b4)
{
    __shared__ float As[16 * 66];
    __shared__ float Bs[16 * 66];
    const int tid = threadIdx.x;
    const int i0 = blockIdx.x * 64, j0 = blockIdx.y * 64;
    const int tx = tid & 15, ty = tid >> 4;
    const int kk = tid & 15, rr = tid >> 4;

    ull acc[4][2] = {};
    for (int k0 = 0; k0 < IND; k0 += 16) {
#pragma unroll
        for (int q = 0; q < 4; q++) {
            int r = rr + q * 16;
            As[kk * 66 + r] = rho_f(data[(size_t)(i0 + r) * IND + k0 + kk]);
            Bs[kk * 66 + r] = W4[(size_t)(j0 + r) * IND + k0 + kk];
        }
        __syncthreads();
#pragma unroll
        for (int k = 0; k < 16; k++) {
            ull a[4];
#pragma unroll
            for (int i = 0; i < 4; i++) {
                float av = As[k * 66 + ty * 4 + i];
                a[i] = pack2(av, av);
            }
            const ull* wp0 = (const ull*)(Bs + k * 66 + tx * 2);
            const ull* wp1 = (const ull*)(Bs + k * 66 + 32 + tx * 2);
            ull w0 = *wp0, w1 = *wp1;
#pragma unroll
            for (int i = 0; i < 4; i++) { fma2(acc[i][0], a[i], w0); fma2(acc[i][1], a[i], w1); }
        }
        __syncthreads();
    }
#pragma unroll
    for (int i = 0; i < 4; i++) {
        size_t row = (size_t)i0 + ty * 4 + i;
        float2 p0 = unpack2(acc[i][0]), p1 = unpack2(acc[i][1]);
        int j0a = j0 + tx * 2, j0b = j0 + 32 + tx * 2;
        *(float2*)(g_X + row * H + j0a) = make_float2(p0.x + b4[j0a], p0.y + b4[j0a + 1]);
        *(float2*)(g_X + row * H + j0b) = make_float2(p1.x + b4[j0b], p1.y + b4[j0b + 1]);
    }
}

// ---------------- fused step kernel ----------------
#define ROWS 64
#define LD   260          // smem row pitch (floats): float4-aligned, bank-spread
#define BK   32
#define NTHR 512
#define STEP_SMEM_FLOATS (2 * ROWS * LD + 2 * BK * H + OUTD * H + ROWS * OUTD)
#define STEP_SMEM_BYTES  (STEP_SMEM_FLOATS * 4)

// Thread (tx, ry): rows {2*ry, 2*ry+1}, col quads {4*tx + 64*p : p=0..3}.
// acc[i][2p], acc[i][2p+1] hold cols 4tx+64p .. +3 for row 2ry+i.
// Weight LDS.128: 16 tx lanes -> 16 consecutive 16B chunks (conflict-free),
// ry halves broadcast-merge. W chunks double-buffered via cp.async.
// NOTE column stride: ulonglong2 = 4 floats, so +64 floats = wr[p * 16].
__device__ __forceinline__ void mm_accum(
    ull (&acc)[2][8], const float* __restrict__ RS,
    const float* __restrict__ Wglob, float* Wc,
    int tid, int rbase, int cb)
{
    const int e = tid * 4;  // this thread's 16B slot within a 32x256 chunk (4 slots)
    // prefetch chunk 0 into buffer 0
#pragma unroll
    for (int q = 0; q < 4; q++)
        cpasync16(Wc + q * 2048 + e, Wglob + q * 2048 + e);
    cpasync_commit();

#pragma unroll 1
    for (int k0 = 0; k0 < H; k0 += BK) {
        float* cur = Wc + ((k0 >> 5) & 1) * (BK * H);
        float* nxt = Wc + (((k0 >> 5) & 1) ^ 1) * (BK * H);
        cpasync_wait0();
        __syncthreads();
        if (k0 + BK < H) {
#pragma unroll
            for (int q = 0; q < 4; q++)
                cpasync16(nxt + q * 2048 + e, Wglob + (size_t)(k0 + BK) * H + q * 2048 + e);
            cpasync_commit();
        }
#pragma unroll 8
        for (int kk = 0; kk < BK; kk++) {
            float a0 = RS[(rbase + 0) * LD + k0 + kk];
            float a1 = RS[(rbase + 1) * LD + k0 + kk];
            ull A0 = pack2(a0, a0), A1 = pack2(a1, a1);
            const ulonglong2* wr = (const ulonglong2*)(cur + kk * H + cb);
#pragma unroll
            for (int p = 0; p < 4; p++) {
                ulonglong2 w = wr[p * 16];       // +64 floats per p (16 x 16B)
                fma2(acc[0][2 * p], A0, w.x); fma2(acc[0][2 * p + 1], A0, w.y);
                fma2(acc[1][2 * p], A1, w.x); fma2(acc[1][2 * p + 1], A1, w.y);
            }
        }
    }
    __syncthreads();
}

__global__ void __launch_bounds__(NTHR, 1) step_kernel(
    int inbuf, int last, float* __restrict__ dout,
    const float* __restrict__ W2, const float* __restrict__ W0,
    const float* __restrict__ b0, const float* __restrict__ b2)
{
    extern __shared__ float sm[];
    float* RS1 = sm;                       // [ROWS][LD]  rho(s1_old)
    float* RS2 = RS1 + ROWS * LD;          // [ROWS][LD]  rho(s2_old)
    float* Wc  = RS2 + ROWS * LD;          // [2][BK][H]  weight chunks (double buf)
    float* W0s = Wc + 2 * BK * H;          // [OUTD][H]
    float* RS0 = W0s + OUTD * H;           // [ROWS][OUTD] rho(s0_old)

    const int tid = threadIdx.x;
    const size_t row0 = (size_t)blockIdx.x * ROWS;

    const float* __restrict__ s0in = g_s0[inbuf];
    const float* __restrict__ s1in = g_s1[inbuf];
    const float* __restrict__ s2in = g_s2[inbuf];
    float* s0out = last ? dout : g_s0[inbuf ^ 1];
    float* s1out = last ? (dout + BATCH * OUTD) : g_s1[inbuf ^ 1];
    float* s2out = last ? (dout + BATCH * OUTD + (size_t)BATCH * H) : g_s2[inbuf ^ 1];

    // ---- stage rho(state) tiles ----
#pragma unroll
    for (int q = 0; q < 8; q++) {
        int e = (q * NTHR + tid) * 4;
        int r = e >> 8, c = e & 255;
        float4 v = *(const float4*)(s1in + row0 * H + e);
        v.x = rho_f(v.x); v.y = rho_f(v.y); v.z = rho_f(v.z); v.w = rho_f(v.w);
        *(float4*)(RS1 + r * LD + c) = v;
        float4 u = *(const float4*)(s2in + row0 * H + e);
        u.x = rho_f(u.x); u.y = rho_f(u.y); u.z = rho_f(u.z); u.w = rho_f(u.w);
        *(float4*)(RS2 + r * LD + c) = u;
    }
    for (int i = tid; i < ROWS * OUTD; i += NTHR)
        RS0[i] = rho_f(s0in[row0 * OUTD + i]);
    for (int i = tid; i < OUTD * H; i += NTHR)
        W0s[i] = W0[i];
    __syncthreads();

    const int tx = tid & 15, ry = tid >> 4;   // ry 0..31
    const int rbase = ry * 2;                 // 2 rows per thread
    const int cb = tx * 4;                    // quads at cb + 64*p

    ull acc[2][8];

    // ================= stage A: s2 update =================
    // n2pre = X + rho(s1) @ W2        (W2[k][j], row-major chunks)
#pragma unroll
    for (int i = 0; i < 2; i++)
#pragma unroll
        for (int p = 0; p < 8; p++) acc[i][p] = 0ULL;
    mm_accum(acc, RS1, W2, Wc, tid, rbase, cb);

#pragma unroll
    for (int i = 0; i < 2; i++) {
        size_t r = row0 + rbase + i;
#pragma unroll
        for (int p = 0; p < 4; p++) {
            int c = cb + 64 * p;
            float4 xo = *(const float4*)(g_X + r * H + c);
            float4 so = *(const float4*)(s2in + r * H + c);
            float2 q0 = unpack2(acc[i][2 * p]), q1 = unpack2(acc[i][2 * p + 1]);
            float4 ov;
            ov.x = rho_f(0.5f * (so.x + ((so.x >= 0.f && so.x <= 1.f) ? (xo.x + q0.x) : 0.f)));
            ov.y = rho_f(0.5f * (so.y + ((so.y >= 0.f && so.y <= 1.f) ? (xo.y + q0.y) : 0.f)));
            ov.z = rho_f(0.5f * (so.z + ((so.z >= 0.f && so.z <= 1.f) ? (xo.z + q1.x) : 0.f)));
            ov.w = rho_f(0.5f * (so.w + ((so.w >= 0.f && so.w <= 1.f) ? (xo.w + q1.y) : 0.f)));
            *(float4*)(s2out + r * H + c) = ov;
        }
    }

    // ================= stage B: s1 update =================
    // n1pre = b2 + rho(s2) @ W2.T + rho(s0) @ W0   (W2.T via g_W2T)
#pragma unroll
    for (int p = 0; p < 4; p++) {
        float4 bv = *(const float4*)(b2 + cb + 64 * p);
        ull b01 = pack2(bv.x, bv.y), b23 = pack2(bv.z, bv.w);
        acc[0][2 * p] = b01; acc[0][2 * p + 1] = b23;
        acc[1][2 * p] = b01; acc[1][2 * p + 1] = b23;
    }
    mm_accum(acc, RS2, g_W2T, Wc, tid, rbase, cb);

#pragma unroll
    for (int o = 0; o < OUTD; o++) {
        float a0 = RS0[(rbase + 0) * OUTD + o];
        float a1 = RS0[(rbase + 1) * OUTD + o];
        ull A0 = pack2(a0, a0), A1 = pack2(a1, a1);
        const ulonglong2* wr = (const ulonglong2*)(W0s + o * H + cb);
#pragma unroll
        for (int p = 0; p < 4; p++) {
            ulonglong2 w = wr[p * 16];           // +64 floats per p
            fma2(acc[0][2 * p], A0, w.x); fma2(acc[0][2 * p + 1], A0, w.y);
            fma2(acc[1][2 * p], A1, w.x); fma2(acc[1][2 * p + 1], A1, w.y);
        }
    }

#pragma unroll
    for (int i = 0; i < 2; i++) {
        size_t r = row0 + rbase + i;
#pragma unroll
        for (int p = 0; p < 4; p++) {
            int c = cb + 64 * p;
            float4 so = *(const float4*)(s1in + r * H + c);
            float2 q0 = unpack2(acc[i][2 * p]), q1 = unpack2(acc[i][2 * p + 1]);
            float4 ov;
            ov.x = rho_f(0.5f * (so.x + ((so.x >= 0.f && so.x <= 1.f) ? q0.x : 0.f)));
            ov.y = rho_f(0.5f * (so.y + ((so.y >= 0.f && so.y <= 1.f) ? q0.y : 0.f)));
            ov.z = rho_f(0.5f * (so.z + ((so.z >= 0.f && so.z <= 1.f) ? q1.x : 0.f)));
            ov.w = rho_f(0.5f * (so.w + ((so.w >= 0.f && so.w <= 1.f) ? q1.y : 0.f)));
            *(float4*)(s1out + r * H + c) = ov;
        }
    }

    // ================= s0 update =================
    // n0 = b0 + rho(s1) @ W0.T ; s0' = clip(0.5*(s0 + n0))   (no rhop gate)
    for (int idx = tid; idx < ROWS * OUTD; idx += NTHR) {
        int o = idx >> 6;          // warp shares o -> W0s reads broadcast
        int r = idx & 63;
        float av = 0.f;
#pragma unroll 8
        for (int k = 0; k < H; k += 4) {
            float4 a = *(const float4*)(RS1 + r * LD + k);
            float4 w = *(const float4*)(W0s + o * H + k);
            av = fmaf(a.x, w.x, fmaf(a.y, w.y, fmaf(a.z, w.z, fmaf(a.w, w.w, av))));
        }
        av += b0[o];
        float s = s0in[(row0 + r) * OUTD + o];
        s0out[(row0 + r) * OUTD + o] = rho_f(0.5f * (s + av));
    }
}

// ---------------- launch ----------------
extern "C" void kernel_launch(void* const* d_in, const int* in_sizes, int n_in,
                              void* d_out, int out_size)
{
    (void)in_sizes; (void)n_in; (void)out_size;
    const float* data = (const float*)d_in[0];
    const float* s0   = (const float*)d_in[1];
    const float* s1   = (const float*)d_in[2];
    const float* s2   = (const float*)d_in[3];
    const float* W0   = (const float*)d_in[4];
    const float* b0   = (const float*)d_in[5];
    const float* W2   = (const float*)d_in[6];
    const float* b2   = (const float*)d_in[7];
    const float* W4   = (const float*)d_in[8];
    const float* b4   = (const float*)d_in[9];
    float* out = (float*)d_out;

    cudaFuncSetAttribute(step_kernel, cudaFuncAttributeMaxDynamicSharedMemorySize,
                         STEP_SMEM_BYTES);

    init_kernel<<<(BATCH * H / 4) / 256, 256>>>(s0, s1, s2, W2);
    x_kernel<<<dim3(BATCH / 64, H / 64), 256>>>(data, W4, b4);
    for (int t = 0; t < TSTEPS; t++) {
        step_kernel<<<BATCH / ROWS, NTHR, STEP_SMEM_BYTES>>>(
            t & 1, t == TSTEPS - 1, out, W2, W0, b0, b2);
    }
}

// round 7
// speedup vs baseline: 1.4659x; 1.4575x over previous
#include <cuda_runtime.h>
#include <cuda_bf16.h>
#include <cstdint>

#define BATCH 16384
#define H 256
#define OUTD 10
#define IND 784
#define TSTEPS 50
#define MROWS 128
#define NTHR 512

typedef unsigned long long ull;

// -------- device scratch --------
__device__ float g_X[BATCH * H];
__device__ float g_s0[2][BATCH * OUTD];
__device__ float g_s1[2][BATCH * H];
__device__ float g_s2[2][BATCH * H];
// bf16 split weight images in [k][n] layout (n contiguous), XOR-swizzled 16B chunks.
// B1[k][n] = W2[k][n]  (P2 = rho(s1) @ W2);  B2[k][n] = W2[n][k]  (P1 = rho(s2) @ W2^T)
__device__ __nv_bfloat16 g_B1hi[H * H], g_B1lo[H * H], g_B2hi[H * H], g_B2lo[H * H];

__device__ __forceinline__ float rho_f(float x) { return fminf(fmaxf(x, 0.0f), 1.0f); }

__device__ __forceinline__ ull pack2(float a, float b) {
    ull r; asm("mov.b64 %0, {%1, %2};" : "=l"(r) : "f"(a), "f"(b)); return r;
}
__device__ __forceinline__ void fma2(ull &d, ull a, ull b) {
    asm("fma.rn.f32x2 %0, %1, %2, %0;" : "+l"(d) : "l"(a), "l"(b));
}
__device__ __forceinline__ float2 unpack2(ull v) {
    float2 f; asm("mov.b64 {%0, %1}, %2;" : "=f"(f.x), "=f"(f.y) : "l"(v)); return f;
}
__device__ __forceinline__ void cpasync16(char* dst, const char* src) {
    unsigned d = (unsigned)__cvta_generic_to_shared(dst);
    asm volatile("cp.async.cg.shared.global [%0], [%1], 16;" :: "r"(d), "l"(src));
}
__device__ __forceinline__ void cpasync_commit() { asm volatile("cp.async.commit_group;"); }
__device__ __forceinline__ void cpasync_wait0()  { asm volatile("cp.async.wait_group 0;"); }
__device__ __forceinline__ void cpasync_wait1()  { asm volatile("cp.async.wait_group 1;"); }

__device__ __forceinline__ uint32_t smem_u32(const void* p) {
    uint32_t a;
    asm("{ .reg .u64 t; cvta.to.shared.u64 t, %1; cvt.u32.u64 %0, t; }" : "=r"(a) : "l"(p));
    return a;
}
__device__ __forceinline__ void ldsm_x4(uint32_t* r, uint32_t addr) {
    asm volatile("ldmatrix.sync.aligned.m8n8.x4.shared.b16 {%0,%1,%2,%3}, [%4];"
                 : "=r"(r[0]), "=r"(r[1]), "=r"(r[2]), "=r"(r[3]) : "r"(addr));
}
__device__ __forceinline__ void ldsm_x4_t(uint32_t* r, uint32_t addr) {
    asm volatile("ldmatrix.sync.aligned.m8n8.x4.trans.shared.b16 {%0,%1,%2,%3}, [%4];"
                 : "=r"(r[0]), "=r"(r[1]), "=r"(r[2]), "=r"(r[3]) : "r"(addr));
}
__device__ __forceinline__ void mma16816(float* c, const uint32_t* a, uint32_t b0, uint32_t b1) {
    asm volatile("mma.sync.aligned.m16n8k16.row.col.f32.bf16.bf16.f32 "
        "{%0,%1,%2,%3}, {%4,%5,%6,%7}, {%8,%9}, {%0,%1,%2,%3};"
        : "+f"(c[0]), "+f"(c[1]), "+f"(c[2]), "+f"(c[3])
        : "r"(a[0]), "r"(a[1]), "r"(a[2]), "r"(a[3]), "r"(b0), "r"(b1));
}

// ---------------- init ----------------
__global__ void __launch_bounds__(256) init_kernel(
    const float* __restrict__ s0, const float* __restrict__ s1,
    const float* __restrict__ s2)
{
    int idx = blockIdx.x * 256 + threadIdx.x;
    ((float4*)g_s1[0])[idx] = ((const float4*)s1)[idx];
    ((float4*)g_s2[0])[idx] = ((const float4*)s2)[idx];
    if (idx < BATCH * OUTD / 4)
        ((float4*)g_s0[0])[idx] = ((const float4*)s0)[idx];
}

// ---------------- build split weight images, [k][n] layout, swizzled ----------------
// element (k, n) at byte: k*512 + (((n>>3) ^ (k&7)) << 4) + (n&7)*2
__global__ void __launch_bounds__(H) img_kernel(const float* __restrict__ W2)
{
    int n = blockIdx.x, k = threadIdx.x;
    uint32_t off = (uint32_t)k * 512u + ((((uint32_t)n >> 3) ^ ((uint32_t)k & 7u)) << 4)
                 + ((uint32_t)n & 7u) * 2u;
    float w1 = W2[k * H + n];
    float w2 = W2[n * H + k];
    __nv_bfloat16 h1 = __float2bfloat16(w1);
    __nv_bfloat16 l1 = __float2bfloat16(w1 - __bfloat162float(h1));
    __nv_bfloat16 h2 = __float2bfloat16(w2);
    __nv_bfloat16 l2 = __float2bfloat16(w2 - __bfloat162float(h2));
    *(__nv_bfloat16*)((char*)g_B1hi + off) = h1;
    *(__nv_bfloat16*)((char*)g_B1lo + off) = l1;
    *(__nv_bfloat16*)((char*)g_B2hi + off) = h2;
    *(__nv_bfloat16*)((char*)g_B2lo + off) = l2;
}

// ---------------- prefix: X = rho(data) @ W4.T + b4 (fp32, once) ----------------
__global__ void __launch_bounds__(256) x_kernel(
    const float* __restrict__ data, const float* __restrict__ W4,
    const float* __restrict__ b4)
{
    __shared__ float As[16 * 66];
    __shared__ float Bs[16 * 66];
    const int tid = threadIdx.x;
    const int i0 = blockIdx.x * 64, j0 = blockIdx.y * 64;
    const int tx = tid & 15, ty = tid >> 4;
    const int kk = tid & 15, rr = tid >> 4;

    ull acc[4][2] = {};
    for (int k0 = 0; k0 < IND; k0 += 16) {
#pragma unroll
        for (int q = 0; q < 4; q++) {
            int r = rr + q * 16;
            As[kk * 66 + r] = rho_f(data[(size_t)(i0 + r) * IND + k0 + kk]);
            Bs[kk * 66 + r] = W4[(size_t)(j0 + r) * IND + k0 + kk];
        }
        __syncthreads();
#pragma unroll
        for (int k = 0; k < 16; k++) {
            ull a[4];
#pragma unroll
            for (int i = 0; i < 4; i++) {
                float av = As[k * 66 + ty * 4 + i];
                a[i] = pack2(av, av);
            }
            ull w0 = *(const ull*)(Bs + k * 66 + tx * 2);
            ull w1 = *(const ull*)(Bs + k * 66 + 32 + tx * 2);
#pragma unroll
            for (int i = 0; i < 4; i++) { fma2(acc[i][0], a[i], w0); fma2(acc[i][1], a[i], w1); }
        }
        __syncthreads();
    }
#pragma unroll
    for (int i = 0; i < 4; i++) {
        size_t row = (size_t)i0 + ty * 4 + i;
        float2 p0 = unpack2(acc[i][0]), p1 = unpack2(acc[i][1]);
        int j0a = j0 + tx * 2, j0b = j0 + 32 + tx * 2;
        *(float2*)(g_X + row * H + j0a) = make_float2(p0.x + b4[j0a], p0.y + b4[j0a + 1]);
        *(float2*)(g_X + row * H + j0b) = make_float2(p1.x + b4[j0b], p1.y + b4[j0b + 1]);
    }
}

// ---------------- SMEM layout (bytes) ----------------
#define SM_A_HI 0
#define SM_A_LO 65536
#define SM_B    131072                 // 2 bufs x (hi 16KB + lo 16KB)
#define SM_W0   196608                 // [10][256] f32
#define SM_RS0  (SM_W0 + OUTD * H * 4) // [128][10] f32
#define SM_B2V  (SM_RS0 + MROWS * OUTD * 4)
#define SM_B0V  (SM_B2V + H * 4)
#define SM_TOTAL (SM_B0V + 64)

// stage rho(state) [128][256] as bf16 hi/lo in swizzled row-major (k contiguous) layout
// element (m, k) at byte: m*512 + (((k>>3) ^ (m&7)) << 4) + (k&7)*2
__device__ __forceinline__ void stage_A(const float* __restrict__ sin, size_t row0,
                                        char* sm, int tid)
{
#pragma unroll
    for (int it = 0; it < 8; it++) {
        int idx = it * NTHR + tid;
        int m = idx >> 5, ch = idx & 31, k = ch << 3;
        float4 v0 = *(const float4*)(sin + (row0 + m) * H + k);
        float4 v1 = *(const float4*)(sin + (row0 + m) * H + k + 4);
        float f[8] = { rho_f(v0.x), rho_f(v0.y), rho_f(v0.z), rho_f(v0.w),
                       rho_f(v1.x), rho_f(v1.y), rho_f(v1.z), rho_f(v1.w) };
        uint32_t hi[4], lo[4];
#pragma unroll
        for (int q = 0; q < 4; q++) {
            __nv_bfloat16 ha = __float2bfloat16(f[2 * q]);
            __nv_bfloat16 hb = __float2bfloat16(f[2 * q + 1]);
            __nv_bfloat16 la = __float2bfloat16(f[2 * q] - __bfloat162float(ha));
            __nv_bfloat16 lb = __float2bfloat16(f[2 * q + 1] - __bfloat162float(hb));
            hi[q] = ((uint32_t)__bfloat16_as_ushort(hb) << 16) | __bfloat16_as_ushort(ha);
            lo[q] = ((uint32_t)__bfloat16_as_ushort(lb) << 16) | __bfloat16_as_ushort(la);
        }
        uint32_t off = (uint32_t)m * 512u + (((uint32_t)(ch ^ (m & 7))) << 4);
        *(uint4*)(sm + SM_A_HI + off) = make_uint4(hi[0], hi[1], hi[2], hi[3]);
        *(uint4*)(sm + SM_A_LO + off) = make_uint4(lo[0], lo[1], lo[2], lo[3]);
    }
}

__global__ void __launch_bounds__(NTHR, 1) step_kernel(
    int inbuf, int last, float* __restrict__ dout,
    const float* __restrict__ W0, const float* __restrict__ b0,
    const float* __restrict__ b2)
{
    extern __shared__ char sm[];
    const uint32_t smb = smem_u32(sm);
    const int tid = threadIdx.x;
    const int lane = tid & 31, wid = tid >> 5;
    const size_t row0 = (size_t)blockIdx.x * MROWS;

    const float* __restrict__ s0in = g_s0[inbuf];
    const float* __restrict__ s1in = g_s1[inbuf];
    const float* __restrict__ s2in = g_s2[inbuf];
    float* s0out = last ? dout : g_s0[inbuf ^ 1];
    float* s1out = last ? (dout + BATCH * OUTD) : g_s1[inbuf ^ 1];
    float* s2out = last ? (dout + BATCH * OUTD + (size_t)BATCH * H) : g_s2[inbuf ^ 1];

    // warp tile: rows wm..wm+31, cols wn..wn+63
    const int wm = (wid & 3) * 32;
    const int wn = (wid >> 2) * 64;

    // small staging
    for (int i = tid; i < OUTD * H; i += NTHR) ((float*)(sm + SM_W0))[i] = W0[i];
    for (int i = tid; i < H; i += NTHR)        ((float*)(sm + SM_B2V))[i] = b2[i];
    if (tid < OUTD)                            ((float*)(sm + SM_B0V))[tid] = b0[tid];
    for (int i = tid; i < MROWS * OUTD; i += NTHR)
        ((float*)(sm + SM_RS0))[i] = rho_f(s0in[row0 * OUTD + i]);
    stage_A(s1in, row0, sm, tid);
    __syncthreads();

    float acc[2][8][4];

    for (int g = 0; g < 2; g++) {
        const char* imgHi = g ? (const char*)g_B2hi : (const char*)g_B1hi;
        const char* imgLo = g ? (const char*)g_B2lo : (const char*)g_B1lo;

#pragma unroll
        for (int i = 0; i < 2; i++)
#pragma unroll
            for (int j = 0; j < 8; j++)
#pragma unroll
                for (int q = 0; q < 4; q++) acc[i][j][q] = 0.f;

        // prefetch chunk 0 -> buf 0
        {
            char* d = sm + SM_B + tid * 32;
            cpasync16(d, imgHi + tid * 32);
            cpasync16(d + 16, imgHi + tid * 32 + 16);
            cpasync16(d + 16384, imgLo + tid * 32);
            cpasync16(d + 16384 + 16, imgLo + tid * 32 + 16);
            cpasync_commit();
        }

#pragma unroll 1
        for (int kc = 0; kc < 8; kc++) {
            const int buf = kc & 1;
            if (kc < 7) {
                char* d = sm + SM_B + (buf ^ 1) * 32768 + tid * 32;
                const char* sh = imgHi + (size_t)(kc + 1) * 16384 + tid * 32;
                const char* sl = imgLo + (size_t)(kc + 1) * 16384 + tid * 32;
                cpasync16(d, sh); cpasync16(d + 16, sh + 16);
                cpasync16(d + 16384, sl); cpasync16(d + 16384 + 16, sl + 16);
                cpasync_commit();
                cpasync_wait1();
            } else {
                cpasync_wait0();
            }
            __syncthreads();

            const uint32_t bbase = smb + SM_B + buf * 32768;
#pragma unroll
            for (int ks = 0; ks < 2; ks++) {
                const int kk = kc * 32 + ks * 16;
                uint32_t ah[2][4], al[2][4];
#pragma unroll
                for (int i = 0; i < 2; i++) {
                    int mr = wm + i * 16 + (lane & 15);
                    uint32_t aoff = (uint32_t)mr * 512u
                                  + ((uint32_t)(((kk >> 3) + (lane >> 4)) ^ (mr & 7)) << 4);
                    ldsm_x4(ah[i], smb + SM_A_HI + aoff);
                    ldsm_x4(al[i], smb + SM_A_LO + aoff);
                }
                const int kl = ks * 16 + (lane & 15);
#pragma unroll
                for (int jp = 0; jp < 4; jp++) {
                    int nch = ((wn + jp * 16) >> 3) + (lane >> 4);
                    uint32_t boff = (uint32_t)kl * 512u
                                  + ((uint32_t)(nch ^ (kl & 7)) << 4);
                    uint32_t bh[4], bl[4];
                    ldsm_x4_t(bh, bbase + boff);
                    ldsm_x4_t(bl, bbase + 16384 + boff);
#pragma unroll
                    for (int h = 0; h < 2; h++) {
                        int j = jp * 2 + h;
#pragma unroll
                        for (int i = 0; i < 2; i++) {
                            mma16816(acc[i][j], ah[i], bh[2 * h], bh[2 * h + 1]);
                            mma16816(acc[i][j], ah[i], bl[2 * h], bl[2 * h + 1]);
                            mma16816(acc[i][j], al[i], bh[2 * h], bh[2 * h + 1]);
                        }
                    }
                }
            }
            __syncthreads();
        }

        if (g == 0) {
            // ---- epilogue s2: s2' = rho(0.5*(s2 + rhop(s2)*(X + P2)))
#pragma unroll
            for (int i = 0; i < 2; i++) {
                int r = wm + i * 16 + (lane >> 2);
#pragma unroll
                for (int j = 0; j < 8; j++) {
                    int c = wn + j * 8 + 2 * (lane & 3);
#pragma unroll
                    for (int half = 0; half < 2; half++) {
                        size_t gr = row0 + r + half * 8;
                        float p0 = acc[i][j][half * 2], p1 = acc[i][j][half * 2 + 1];
                        float2 xo = *(const float2*)(g_X + gr * H + c);
                        float2 so = *(const float2*)(s2in + gr * H + c);
                        float2 ov;
                        ov.x = rho_f(0.5f * (so.x + ((so.x >= 0.f && so.x <= 1.f) ? (xo.x + p0) : 0.f)));
                        ov.y = rho_f(0.5f * (so.y + ((so.y >= 0.f && so.y <= 1.f) ? (xo.y + p1) : 0.f)));
                        *(float2*)(s2out + gr * H + c) = ov;
                    }
                }
            }
            // ---- s0 update: s0' = rho(0.5*(s0 + b0 + rho(s1) @ W0.T))
            const float* W0s = (const float*)(sm + SM_W0);
            const float* b0s = (const float*)(sm + SM_B0V);
            for (int task = tid; task < MROWS * OUTD; task += NTHR) {
                int r = task / OUTD, o = task - r * OUTD;
                const float* srow = s1in + (row0 + r) * H;
                const float* wrow = W0s + o * H;
                float a = b0s[o];
#pragma unroll 8
                for (int k = 0; k < H; k += 4) {
                    float4 sv = *(const float4*)(srow + k);
                    float4 wv = *(const float4*)(wrow + k);
                    a = fmaf(rho_f(sv.x), wv.x, fmaf(rho_f(sv.y), wv.y,
                        fmaf(rho_f(sv.z), wv.z, fmaf(rho_f(sv.w), wv.w, a))));
                }
                float s = s0in[(row0 + r) * OUTD + o];
                s0out[(row0 + r) * OUTD + o] = rho_f(0.5f * (s + a));
            }
            __syncthreads();
            stage_A(s2in, row0, sm, tid);
            __syncthreads();
        } else {
            // ---- epilogue s1: pre = P1 + b2 + rho(s0) @ W0
            const float* W0s = (const float*)(sm + SM_W0);
            const float* b2s = (const float*)(sm + SM_B2V);
            const float* rs0 = (const float*)(sm + SM_RS0);
#pragma unroll
            for (int i = 0; i < 2; i++) {
                int r = wm + i * 16 + (lane >> 2);
#pragma unroll
                for (int j = 0; j < 8; j++) {
                    int c = wn + j * 8 + 2 * (lane & 3);
                    float b2x = b2s[c], b2y = b2s[c + 1];
#pragma unroll
                    for (int half = 0; half < 2; half++) {
                        int rr = r + half * 8;
                        size_t gr = row0 + rr;
                        float p0 = acc[i][j][half * 2] + b2x;
                        float p1 = acc[i][j][half * 2 + 1] + b2y;
#pragma unroll
                        for (int o = 0; o < OUTD; o++) {
                            float a = rs0[rr * OUTD + o];
                            p0 = fmaf(a, W0s[o * H + c], p0);
                            p1 = fmaf(a, W0s[o * H + c + 1], p1);
                        }
                        float2 so = *(const float2*)(s1in + gr * H + c);
                        float2 ov;
                        ov.x = rho_f(0.5f * (so.x + ((so.x >= 0.f && so.x <= 1.f) ? p0 : 0.f)));
                        ov.y = rho_f(0.5f * (so.y + ((so.y >= 0.f && so.y <= 1.f) ? p1 : 0.f)));
                        *(float2*)(s1out + gr * H + c) = ov;
                    }
                }
            }
        }
    }
}

// ---------------- launch ----------------
extern "C" void kernel_launch(void* const* d_in, const int* in_sizes, int n_in,
                              void* d_out, int out_size)
{
    (void)in_sizes; (void)n_in; (void)out_size;
    const float* data = (const float*)d_in[0];
    const float* s0   = (const float*)d_in[1];
    const float* s1   = (const float*)d_in[2];
    const float* s2   = (const float*)d_in[3];
    const float* W0   = (const float*)d_in[4];
    const float* b0   = (const float*)d_in[5];
    const float* W2   = (const float*)d_in[6];
    const float* b2   = (const float*)d_in[7];
    const float* W4   = (const float*)d_in[8];
    const float* b4   = (const float*)d_in[9];
    float* out = (float*)d_out;

    cudaFuncSetAttribute(step_kernel, cudaFuncAttributeMaxDynamicSharedMemorySize, SM_TOTAL);

    init_kernel<<<(BATCH * H / 4) / 256, 256>>>(s0, s1, s2);
    img_kernel<<<H, H>>>(W2);
    x_kernel<<<dim3(BATCH / 64, H / 64), 256>>>(data, W4, b4);
    for (int t = 0; t < TSTEPS; t++) {
        step_kernel<<<BATCH / MROWS, NTHR, SM_TOTAL>>>(
            t & 1, t == TSTEPS - 1, out, W0, b0, b2);
    }
}